// round 14
// baseline (speedup 1.0000x reference)
#include <cuda_runtime.h>
#include <cuda_bf16.h>
#include <cstdint>

#define B_SZ   16
#define N_SZ   128
#define ROWS   2048        // B*N
#define K_NB   16
#define D_SZ   512
#define C_SZ   2048        // 4*D
#define ALPHA  0.2f
#define BN_EPS 1e-5f
#define L2_EPS 1e-12f

// ---------------- device scratch (no allocations allowed) ----------------
__device__ float g_a_self[ROWS];
__device__ float g_a_nei[ROWS];
__device__ float g_y[ROWS * D_SZ];          // x @ Wn^T + Wn_b   (4 MB)
__device__ float g_h[ROWS * C_SZ];          // concat rows       (16 MB)
__device__ float g_sum[C_SZ];
__device__ float g_sumsq[C_SZ];
__device__ float g_w[3 * ROWS * K_NB];      // softmax weights
__device__ int   g_ni[3 * ROWS * K_NB];     // neighbor row ids (global)

__device__ __nv_bfloat16 g_xhi[ROWS * D_SZ];
__device__ __nv_bfloat16 g_xlo[ROWS * D_SZ];
__device__ __nv_bfloat16 g_wxhi[D_SZ * D_SZ];
__device__ __nv_bfloat16 g_wxlo[D_SZ * D_SZ];
__device__ __nv_bfloat16 g_wnhi[D_SZ * D_SZ];
__device__ __nv_bfloat16 g_wnlo[D_SZ * D_SZ];

// ---------------- kernel 1: attention dot products + zero stats ----------
__global__ void k_prep(const float* __restrict__ x, const float* __restrict__ Wa) {
    int tid = threadIdx.x;
    int gid = blockIdx.x * 256 + tid;
    if (gid < C_SZ) { g_sum[gid] = 0.f; g_sumsq[gid] = 0.f; }

    int wid = tid >> 5, lane = tid & 31;
    int row = blockIdx.x * 8 + wid;
    const float* xr = x + (size_t)row * D_SZ;
    float s1 = 0.f, s2 = 0.f;
    #pragma unroll 4
    for (int i = lane; i < D_SZ; i += 32) {
        float v = xr[i];
        s1 += v * Wa[i];
        s2 += v * Wa[D_SZ + i];
    }
    #pragma unroll
    for (int o = 16; o > 0; o >>= 1) {
        s1 += __shfl_down_sync(0xffffffffu, s1, o);
        s2 += __shfl_down_sync(0xffffffffu, s2, o);
    }
    if (lane == 0) { g_a_self[row] = s1; g_a_nei[row] = s2; }
}

// ---------------- kernel 2: per-(row,branch) softmax weights --------------
__global__ void k_w(const int* __restrict__ i1, const int* __restrict__ i2,
                    const int* __restrict__ i3) {
    int g = (blockIdx.x * 128 + threadIdx.x) >> 5;
    int lane = threadIdx.x & 31;
    int row = g / 3;
    int br = g - row * 3;
    int b = row >> 7, n = row & 127;
    const int* ip = (br == 0) ? i1 : (br == 1) ? i2 : i3;
    int k = lane & 15;
    int m = ip[n * K_NB + k];
    float e = g_a_self[row] + g_a_nei[b * N_SZ + m];
    e = (e > 0.f) ? e : ALPHA * e;

    float mx = e;
    #pragma unroll
    for (int o = 8; o > 0; o >>= 1) mx = fmaxf(mx, __shfl_xor_sync(0xffffffffu, mx, o, 16));
    float ev = __expf(e - mx);
    float s = ev;
    #pragma unroll
    for (int o = 8; o > 0; o >>= 1) s += __shfl_xor_sync(0xffffffffu, s, o, 16);
    float w = ev / s;

    if (lane < 16) {
        g_w[(br * ROWS + row) * K_NB + k] = w;
        g_ni[(br * ROWS + row) * K_NB + k] = b * N_SZ + m;
    }
}

// ---------------- kernel 3: fp32 -> bf16 hi/lo split ----------------------
__device__ __forceinline__ void split1(float v, __nv_bfloat16& h, __nv_bfloat16& l) {
    h = __float2bfloat16_rn(v);
    l = __float2bfloat16_rn(v - __bfloat162float(h));
}

__device__ __forceinline__ void split4_store(float4 v, __nv_bfloat16* hi, __nv_bfloat16* lo, int idx4) {
    __nv_bfloat16 h0, h1, h2, h3, l0, l1, l2, l3;
    split1(v.x, h0, l0); split1(v.y, h1, l1);
    split1(v.z, h2, l2); split1(v.w, h3, l3);
    __nv_bfloat162 ph0(h0, h1), ph1(h2, h3), pl0(l0, l1), pl1(l2, l3);
    uint2 uh, ul;
    uh.x = *(uint32_t*)&ph0; uh.y = *(uint32_t*)&ph1;
    ul.x = *(uint32_t*)&pl0; ul.y = *(uint32_t*)&pl1;
    *(uint2*)&hi[idx4 * 4] = uh;
    *(uint2*)&lo[idx4 * 4] = ul;
}

__global__ void k_conv(const float* __restrict__ x, const float* __restrict__ Wx,
                       const float* __restrict__ Wn) {
    int t = blockIdx.x * 256 + threadIdx.x;
    split4_store(((const float4*)x)[t], g_xhi, g_xlo, t);
    if (t < 65536) {
        split4_store(((const float4*)Wx)[t], g_wxhi, g_wxlo, t);
    } else if (t < 131072) {
        int u = t - 65536;
        split4_store(((const float4*)Wn)[u], g_wnhi, g_wnlo, u);
    }
}

// ---------------- kernel 4: tensor-core GEMMs (R8 winner) -----------------
// Block tile 128x128, 16 warps (4m x 4n), warp tile 32x32, BK=32.
#define SSTRIDE 40

#define MMA16816(d, a, b0v, b1v) \
    asm volatile("mma.sync.aligned.m16n8k16.row.col.f32.bf16.bf16.f32 " \
        "{%0,%1,%2,%3}, {%4,%5,%6,%7}, {%8,%9}, {%0,%1,%2,%3};" \
        : "+f"(d[0]), "+f"(d[1]), "+f"(d[2]), "+f"(d[3]) \
        : "r"(a[0]), "r"(a[1]), "r"(a[2]), "r"(a[3]), "r"(b0v), "r"(b1v))

__device__ __forceinline__ void ldsm_x4(uint32_t* r, uint32_t a) {
    asm volatile("ldmatrix.sync.aligned.m8n8.x4.shared.b16 {%0,%1,%2,%3}, [%4];"
                 : "=r"(r[0]), "=r"(r[1]), "=r"(r[2]), "=r"(r[3]) : "r"(a));
}

__global__ __launch_bounds__(512) void k_tc(const float* __restrict__ Wxb,
                                            const float* __restrict__ Wnb) {
    __shared__ __nv_bfloat16 Ash[128 * SSTRIDE];
    __shared__ __nv_bfloat16 Asl[128 * SSTRIDE];
    __shared__ __nv_bfloat16 Bsh[128 * SSTRIDE];
    __shared__ __nv_bfloat16 Bsl[128 * SSTRIDE];

    int z = blockIdx.z;
    const __nv_bfloat16* Bhi = z ? g_wnhi : g_wxhi;
    const __nv_bfloat16* Blo = z ? g_wnlo : g_wxlo;
    const float* bias = z ? Wnb : Wxb;
    float* C = z ? g_y : g_h;
    int ldc = z ? D_SZ : C_SZ;

    int tid = threadIdx.x;
    int lane = tid & 31;
    int wid = tid >> 5;                  // 0..15
    int wm = (wid >> 2) * 32;
    int wn = (wid & 3) * 32;
    int bm = blockIdx.y * 128;
    int bn = blockIdx.x * 128;

    int l0r = tid >> 2;                  // 0..127
    int l0c = (tid & 3) * 8;             // 0,8,16,24

    float acc[2][4][4];
    #pragma unroll
    for (int i = 0; i < 2; i++)
        #pragma unroll
        for (int j = 0; j < 4; j++)
            #pragma unroll
            for (int q = 0; q < 4; q++) acc[i][j][q] = 0.f;

    uint4 ah0 = *(const uint4*)&g_xhi[(size_t)(bm + l0r) * D_SZ + l0c];
    uint4 al0 = *(const uint4*)&g_xlo[(size_t)(bm + l0r) * D_SZ + l0c];
    uint4 bh0 = *(const uint4*)&Bhi[(size_t)(bn + l0r) * D_SZ + l0c];
    uint4 bl0 = *(const uint4*)&Blo[(size_t)(bn + l0r) * D_SZ + l0c];

    int m_row = lane & 15, m_coff = (lane >> 4) * 8;

    for (int k0 = 0; k0 < D_SZ; k0 += 32) {
        __syncthreads();
        *(uint4*)&Ash[l0r * SSTRIDE + l0c] = ah0;
        *(uint4*)&Asl[l0r * SSTRIDE + l0c] = al0;
        *(uint4*)&Bsh[l0r * SSTRIDE + l0c] = bh0;
        *(uint4*)&Bsl[l0r * SSTRIDE + l0c] = bl0;
        __syncthreads();

        if (k0 + 32 < D_SZ) {
            int kn = k0 + 32;
            ah0 = *(const uint4*)&g_xhi[(size_t)(bm + l0r) * D_SZ + kn + l0c];
            al0 = *(const uint4*)&g_xlo[(size_t)(bm + l0r) * D_SZ + kn + l0c];
            bh0 = *(const uint4*)&Bhi[(size_t)(bn + l0r) * D_SZ + kn + l0c];
            bl0 = *(const uint4*)&Blo[(size_t)(bn + l0r) * D_SZ + kn + l0c];
        }

        #pragma unroll
        for (int ks = 0; ks < 2; ks++) {
            int kc = ks * 16;
            uint32_t afh[2][4], afl[2][4];
            #pragma unroll
            for (int mf = 0; mf < 2; mf++) {
                int off = (wm + mf * 16 + m_row) * SSTRIDE + kc + m_coff;
                ldsm_x4(afh[mf], (uint32_t)__cvta_generic_to_shared(&Ash[off]));
                ldsm_x4(afl[mf], (uint32_t)__cvta_generic_to_shared(&Asl[off]));
            }
            uint32_t bfh[4][2], bfl[4][2];
            #pragma unroll
            for (int pr = 0; pr < 2; pr++) {
                int off = (wn + pr * 16 + m_row) * SSTRIDE + kc + m_coff;
                uint32_t r[4];
                ldsm_x4(r, (uint32_t)__cvta_generic_to_shared(&Bsh[off]));
                bfh[pr * 2][0] = r[0]; bfh[pr * 2][1] = r[2];
                bfh[pr * 2 + 1][0] = r[1]; bfh[pr * 2 + 1][1] = r[3];
                ldsm_x4(r, (uint32_t)__cvta_generic_to_shared(&Bsl[off]));
                bfl[pr * 2][0] = r[0]; bfl[pr * 2][1] = r[2];
                bfl[pr * 2 + 1][0] = r[1]; bfl[pr * 2 + 1][1] = r[3];
            }
            #pragma unroll
            for (int nf = 0; nf < 4; nf++) {
                #pragma unroll
                for (int mf = 0; mf < 2; mf++) {
                    MMA16816(acc[mf][nf], afh[mf], bfh[nf][0], bfh[nf][1]);
                    MMA16816(acc[mf][nf], afh[mf], bfl[nf][0], bfl[nf][1]);
                    MMA16816(acc[mf][nf], afl[mf], bfh[nf][0], bfh[nf][1]);
                }
            }
        }
    }

    #pragma unroll
    for (int nf = 0; nf < 4; nf++) {
        int cidx = bn + wn + nf * 8 + (lane & 3) * 2;
        float2 bi = *(const float2*)&bias[cidx];
        #pragma unroll
        for (int mf = 0; mf < 2; mf++) {
            int r = bm + wm + mf * 16 + (lane >> 2);
            float2 v0, v1;
            v0.x = acc[mf][nf][0] + bi.x; v0.y = acc[mf][nf][1] + bi.y;
            v1.x = acc[mf][nf][2] + bi.x; v1.y = acc[mf][nf][3] + bi.y;
            *(float2*)&C[(size_t)r * ldc + cidx] = v0;
            *(float2*)&C[(size_t)(r + 8) * ldc + cidx] = v1;
        }
    }
}

// ---------------- kernel 5: batched gather-aggregate ----------------------
// 512 threads (16 warps). Two tasks per warp (half-warp each), float4/lane.
__global__ __launch_bounds__(512) void k_gather() {
    __shared__ float y_s[128 * 64];          // 32 KB
    __shared__ float wbuf[16][2][16];
    __shared__ int   nbuf[16][2][16];

    int ch = blockIdx.x, b = blockIdx.y;
    int tid = threadIdx.x;

    const float4* y4 = (const float4*)g_y;
    #pragma unroll
    for (int it = 0; it < 4; it++) {
        int idx = it * 512 + tid;
        int m = idx >> 4, c4 = idx & 15;
        ((float4*)y_s)[idx] = y4[(size_t)(b * N_SZ + m) * 128 + ch * 16 + c4];
    }
    __syncthreads();

    int wid = tid >> 5, lane = tid & 31;
    int h = lane >> 4, L = lane & 15;
    const float4* ys4 = (const float4*)y_s;

    #pragma unroll 2
    for (int it = 0; it < 12; it++) {
        int t = wid * 24 + it * 2 + h;
        int br = t >> 7, n = t & 127;
        int row = b * N_SZ + n;
        int base = (br * ROWS + row) * K_NB + L;
        wbuf[wid][h][L] = g_w[base];
        nbuf[wid][h][L] = g_ni[base] - b * N_SZ;
        __syncwarp();

        float4 acc = make_float4(0.f, 0.f, 0.f, 0.f);
        #pragma unroll
        for (int k = 0; k < 16; k++) {
            float wk = wbuf[wid][h][k];
            int   mk = nbuf[wid][h][k];
            float4 v = ys4[mk * 16 + L];
            acc.x += wk * v.x; acc.y += wk * v.y;
            acc.z += wk * v.z; acc.w += wk * v.w;
        }
        *(float4*)&g_h[(size_t)row * C_SZ + (br + 1) * D_SZ + ch * 64 + L * 4] = acc;
        __syncwarp();
    }
}

// ---------------- kernel 6: L2 norm + relu + channel stats (fused) --------
// 512 blocks x 4 rows, 512 threads; one float4 of channels per thread.
// Register-accumulated stats, 8 atomics per thread at the end.
__global__ __launch_bounds__(512) void k_epi() {
    int r0 = blockIdx.x * 4;
    int tid = threadIdx.x;
    int wid = tid >> 5;
    __shared__ float red[17];

    float4 s = make_float4(0.f, 0.f, 0.f, 0.f);
    float4 q = make_float4(0.f, 0.f, 0.f, 0.f);

    for (int r = r0; r < r0 + 4; r++) {
        float4* h4 = (float4*)&g_h[(size_t)r * C_SZ];
        float4 v = h4[tid];
        float ss = v.x * v.x + v.y * v.y + v.z * v.z + v.w * v.w;
        #pragma unroll
        for (int o = 16; o > 0; o >>= 1) ss += __shfl_down_sync(0xffffffffu, ss, o);
        if ((tid & 31) == 0) red[wid] = ss;
        __syncthreads();
        if (tid == 0) {
            float t = 0.f;
            #pragma unroll
            for (int i = 0; i < 16; i++) t += red[i];
            red[16] = 1.f / fmaxf(sqrtf(t), L2_EPS);
        }
        __syncthreads();
        float inv = red[16];

        v.x = fmaxf(v.x * inv, 0.f); v.y = fmaxf(v.y * inv, 0.f);
        v.z = fmaxf(v.z * inv, 0.f); v.w = fmaxf(v.w * inv, 0.f);
        h4[tid] = v;

        s.x += v.x; s.y += v.y; s.z += v.z; s.w += v.w;
        q.x += v.x * v.x; q.y += v.y * v.y; q.z += v.z * v.z; q.w += v.w * v.w;
        __syncthreads();
    }

    int c = tid * 4;
    atomicAdd(&g_sum[c + 0], s.x); atomicAdd(&g_sum[c + 1], s.y);
    atomicAdd(&g_sum[c + 2], s.z); atomicAdd(&g_sum[c + 3], s.w);
    atomicAdd(&g_sumsq[c + 0], q.x); atomicAdd(&g_sumsq[c + 1], q.y);
    atomicAdd(&g_sumsq[c + 2], q.z); atomicAdd(&g_sumsq[c + 3], q.w);
}

// ---------------- kernel 7: batchnorm affine -> output --------------------
__global__ void k_final(const float* __restrict__ gamma, const float* __restrict__ beta,
                        float* __restrict__ out) {
    int gid = blockIdx.x * 256 + threadIdx.x;
    int e = gid * 4;
    int c = e & (C_SZ - 1);

    float4 h  = *(const float4*)&g_h[e];
    float4 sm = *(const float4*)&g_sum[c];
    float4 sq = *(const float4*)&g_sumsq[c];
    float4 ga = *(const float4*)&gamma[c];
    float4 be = *(const float4*)&beta[c];

    const float invn = 1.f / (float)ROWS;
    float4 o;
    { float mu = sm.x * invn; float var = sq.x * invn - mu * mu;
      o.x = (h.x - mu) * rsqrtf(var + BN_EPS) * ga.x + be.x; }
    { float mu = sm.y * invn; float var = sq.y * invn - mu * mu;
      o.y = (h.y - mu) * rsqrtf(var + BN_EPS) * ga.y + be.y; }
    { float mu = sm.z * invn; float var = sq.z * invn - mu * mu;
      o.z = (h.z - mu) * rsqrtf(var + BN_EPS) * ga.z + be.z; }
    { float mu = sm.w * invn; float var = sq.w * invn - mu * mu;
      o.w = (h.w - mu) * rsqrtf(var + BN_EPS) * ga.w + be.w; }
    *(float4*)&out[e] = o;
}

// ---------------- launch ---------------------------------------------------
extern "C" void kernel_launch(void* const* d_in, const int* in_sizes, int n_in,
                              void* d_out, int out_size) {
    const float* x     = (const float*)d_in[0];
    const int*   i1    = (const int*)  d_in[1];
    const int*   i2    = (const int*)  d_in[2];
    const int*   i3    = (const int*)  d_in[3];
    const float* Wxw   = (const float*)d_in[4];
    const float* Wxb   = (const float*)d_in[5];
    const float* Wnw   = (const float*)d_in[6];
    const float* Wnb   = (const float*)d_in[7];
    const float* Wa    = (const float*)d_in[8];
    const float* gamma = (const float*)d_in[9];
    const float* beta  = (const float*)d_in[10];
    float* out = (float*)d_out;

    k_prep<<<256, 256>>>(x, Wa);
    k_w<<<1536, 128>>>(i1, i2, i3);
    k_conv<<<1024, 256>>>(x, Wxw, Wnw);
    k_tc<<<dim3(4, 16, 2), 512>>>(Wxb, Wnb);
    k_gather<<<dim3(8, 16), 512>>>();
    k_epi<<<512, 512>>>();
    k_final<<<(ROWS * C_SZ) / (256 * 4), 256>>>(gamma, beta, out);
}

// round 15
// speedup vs baseline: 1.4138x; 1.4138x over previous
#include <cuda_runtime.h>
#include <cuda_fp16.h>
#include <cstdint>

#define B_SZ   16
#define N_SZ   128
#define ROWS   2048        // B*N
#define K_NB   16
#define D_SZ   512
#define C_SZ   2048        // 4*D
#define ALPHA  0.2f
#define BN_EPS 1e-5f
#define L2_EPS 1e-12f

// ---------------- device scratch (no allocations allowed) ----------------
__device__ float g_a_self[ROWS];
__device__ float g_a_nei[ROWS];
__device__ float g_y[ROWS * D_SZ];          // x @ Wn^T + Wn_b   (4 MB)
__device__ float g_h[ROWS * C_SZ];          // concat rows       (16 MB)
__device__ float g_sum[C_SZ];
__device__ float g_sumsq[C_SZ];
__device__ float g_w[3 * ROWS * K_NB];      // softmax weights
__device__ int   g_ni[3 * ROWS * K_NB];     // neighbor row ids (global)

__device__ __half g_xh[ROWS * D_SZ];        // x hi (fp16)
__device__ __half g_xl[ROWS * D_SZ];        // x lo (fp16)
__device__ __half g_wx16[D_SZ * D_SZ];      // Wx (fp16)
__device__ __half g_wn16[D_SZ * D_SZ];      // Wn (fp16)

// ---------------- kernel 1: attention dot products + zero stats ----------
__global__ void k_prep(const float* __restrict__ x, const float* __restrict__ Wa) {
    int tid = threadIdx.x;
    int gid = blockIdx.x * 256 + tid;
    if (gid < C_SZ) { g_sum[gid] = 0.f; g_sumsq[gid] = 0.f; }

    int wid = tid >> 5, lane = tid & 31;
    int row = blockIdx.x * 8 + wid;
    const float* xr = x + (size_t)row * D_SZ;
    float s1 = 0.f, s2 = 0.f;
    #pragma unroll 4
    for (int i = lane; i < D_SZ; i += 32) {
        float v = xr[i];
        s1 += v * Wa[i];
        s2 += v * Wa[D_SZ + i];
    }
    #pragma unroll
    for (int o = 16; o > 0; o >>= 1) {
        s1 += __shfl_down_sync(0xffffffffu, s1, o);
        s2 += __shfl_down_sync(0xffffffffu, s2, o);
    }
    if (lane == 0) { g_a_self[row] = s1; g_a_nei[row] = s2; }
}

// ---------------- kernel 2: per-(row,branch) softmax weights --------------
__global__ void k_w(const int* __restrict__ i1, const int* __restrict__ i2,
                    const int* __restrict__ i3) {
    int g = (blockIdx.x * 128 + threadIdx.x) >> 5;
    int lane = threadIdx.x & 31;
    int row = g / 3;
    int br = g - row * 3;
    int b = row >> 7, n = row & 127;
    const int* ip = (br == 0) ? i1 : (br == 1) ? i2 : i3;
    int k = lane & 15;
    int m = ip[n * K_NB + k];
    float e = g_a_self[row] + g_a_nei[b * N_SZ + m];
    e = (e > 0.f) ? e : ALPHA * e;

    float mx = e;
    #pragma unroll
    for (int o = 8; o > 0; o >>= 1) mx = fmaxf(mx, __shfl_xor_sync(0xffffffffu, mx, o, 16));
    float ev = __expf(e - mx);
    float s = ev;
    #pragma unroll
    for (int o = 8; o > 0; o >>= 1) s += __shfl_xor_sync(0xffffffffu, s, o, 16);
    float w = ev / s;

    if (lane < 16) {
        g_w[(br * ROWS + row) * K_NB + k] = w;
        g_ni[(br * ROWS + row) * K_NB + k] = b * N_SZ + m;
    }
}

// ---------------- kernel 3: fp32 -> fp16 conversion -----------------------
// x -> hi/lo fp16 pair; Wx, Wn -> single fp16.
__global__ void k_conv(const float* __restrict__ x, const float* __restrict__ Wx,
                       const float* __restrict__ Wn) {
    int t = blockIdx.x * 256 + threadIdx.x;

    {
        float4 v = ((const float4*)x)[t];
        __half h0 = __float2half_rn(v.x);
        __half h1 = __float2half_rn(v.y);
        __half h2 = __float2half_rn(v.z);
        __half h3 = __float2half_rn(v.w);
        __half l0 = __float2half_rn(v.x - __half2float(h0));
        __half l1 = __float2half_rn(v.y - __half2float(h1));
        __half l2 = __float2half_rn(v.z - __half2float(h2));
        __half l3 = __float2half_rn(v.w - __half2float(h3));
        __half2 ph0(h0, h1), ph1(h2, h3), pl0(l0, l1), pl1(l2, l3);
        uint2 uh, ul;
        uh.x = *(uint32_t*)&ph0; uh.y = *(uint32_t*)&ph1;
        ul.x = *(uint32_t*)&pl0; ul.y = *(uint32_t*)&pl1;
        *(uint2*)&g_xh[t * 4] = uh;
        *(uint2*)&g_xl[t * 4] = ul;
    }

    if (t < 131072) {
        const float* Wsrc = (t < 65536) ? Wx : Wn;
        __half* Wdst = (t < 65536) ? g_wx16 : g_wn16;
        int u = (t < 65536) ? t : t - 65536;
        float4 v = ((const float4*)Wsrc)[u];
        __half2 p0(__float2half_rn(v.x), __float2half_rn(v.y));
        __half2 p1(__float2half_rn(v.z), __float2half_rn(v.w));
        uint2 uw;
        uw.x = *(uint32_t*)&p0; uw.y = *(uint32_t*)&p1;
        *(uint2*)&Wdst[u * 4] = uw;
    }
}

// ---------------- kernel 4: tensor-core GEMMs (fp16, 2 passes) ------------
// Block tile 128x128, 16 warps (4m x 4n), warp tile 32x32, BK=32.
// C = xh*W + xl*W, fp32 accumulate.
#define SSTRIDE 40

#define MMAF16(d, a, b0v, b1v) \
    asm volatile("mma.sync.aligned.m16n8k16.row.col.f32.f16.f16.f32 " \
        "{%0,%1,%2,%3}, {%4,%5,%6,%7}, {%8,%9}, {%0,%1,%2,%3};" \
        : "+f"(d[0]), "+f"(d[1]), "+f"(d[2]), "+f"(d[3]) \
        : "r"(a[0]), "r"(a[1]), "r"(a[2]), "r"(a[3]), "r"(b0v), "r"(b1v))

__device__ __forceinline__ void ldsm_x4(uint32_t* r, uint32_t a) {
    asm volatile("ldmatrix.sync.aligned.m8n8.x4.shared.b16 {%0,%1,%2,%3}, [%4];"
                 : "=r"(r[0]), "=r"(r[1]), "=r"(r[2]), "=r"(r[3]) : "r"(a));
}

__global__ __launch_bounds__(512) void k_tc(const float* __restrict__ Wxb,
                                            const float* __restrict__ Wnb) {
    __shared__ __half Ash[128 * SSTRIDE];
    __shared__ __half Asl[128 * SSTRIDE];
    __shared__ __half Bs[128 * SSTRIDE];

    int z = blockIdx.z;
    const __half* Wm = z ? g_wn16 : g_wx16;
    const float* bias = z ? Wnb : Wxb;
    float* C = z ? g_y : g_h;
    int ldc = z ? D_SZ : C_SZ;

    int tid = threadIdx.x;
    int lane = tid & 31;
    int wid = tid >> 5;                  // 0..15
    int wm = (wid >> 2) * 32;
    int wn = (wid & 3) * 32;
    int bm = blockIdx.y * 128;
    int bn = blockIdx.x * 128;

    int l0r = tid >> 2;                  // 0..127
    int l0c = (tid & 3) * 8;             // 0,8,16,24

    float acc[2][4][4];
    #pragma unroll
    for (int i = 0; i < 2; i++)
        #pragma unroll
        for (int j = 0; j < 4; j++)
            #pragma unroll
            for (int q = 0; q < 4; q++) acc[i][j][q] = 0.f;

    uint4 ah0 = *(const uint4*)&g_xh[(size_t)(bm + l0r) * D_SZ + l0c];
    uint4 al0 = *(const uint4*)&g_xl[(size_t)(bm + l0r) * D_SZ + l0c];
    uint4 b0  = *(const uint4*)&Wm[(size_t)(bn + l0r) * D_SZ + l0c];

    int m_row = lane & 15, m_coff = (lane >> 4) * 8;

    for (int k0 = 0; k0 < D_SZ; k0 += 32) {
        __syncthreads();
        *(uint4*)&Ash[l0r * SSTRIDE + l0c] = ah0;
        *(uint4*)&Asl[l0r * SSTRIDE + l0c] = al0;
        *(uint4*)&Bs[l0r * SSTRIDE + l0c]  = b0;
        __syncthreads();

        if (k0 + 32 < D_SZ) {
            int kn = k0 + 32;
            ah0 = *(const uint4*)&g_xh[(size_t)(bm + l0r) * D_SZ + kn + l0c];
            al0 = *(const uint4*)&g_xl[(size_t)(bm + l0r) * D_SZ + kn + l0c];
            b0  = *(const uint4*)&Wm[(size_t)(bn + l0r) * D_SZ + kn + l0c];
        }

        #pragma unroll
        for (int ks = 0; ks < 2; ks++) {
            int kc = ks * 16;
            uint32_t afh[2][4], afl[2][4];
            #pragma unroll
            for (int mf = 0; mf < 2; mf++) {
                int off = (wm + mf * 16 + m_row) * SSTRIDE + kc + m_coff;
                ldsm_x4(afh[mf], (uint32_t)__cvta_generic_to_shared(&Ash[off]));
                ldsm_x4(afl[mf], (uint32_t)__cvta_generic_to_shared(&Asl[off]));
            }
            uint32_t bf[4][2];
            #pragma unroll
            for (int pr = 0; pr < 2; pr++) {
                int off = (wn + pr * 16 + m_row) * SSTRIDE + kc + m_coff;
                uint32_t r[4];
                ldsm_x4(r, (uint32_t)__cvta_generic_to_shared(&Bs[off]));
                bf[pr * 2][0] = r[0]; bf[pr * 2][1] = r[2];
                bf[pr * 2 + 1][0] = r[1]; bf[pr * 2 + 1][1] = r[3];
            }
            #pragma unroll
            for (int nf = 0; nf < 4; nf++) {
                #pragma unroll
                for (int mf = 0; mf < 2; mf++) {
                    MMAF16(acc[mf][nf], afh[mf], bf[nf][0], bf[nf][1]);
                    MMAF16(acc[mf][nf], afl[mf], bf[nf][0], bf[nf][1]);
                }
            }
        }
    }

    #pragma unroll
    for (int nf = 0; nf < 4; nf++) {
        int cidx = bn + wn + nf * 8 + (lane & 3) * 2;
        float2 bi = *(const float2*)&bias[cidx];
        #pragma unroll
        for (int mf = 0; mf < 2; mf++) {
            int r = bm + wm + mf * 16 + (lane >> 2);
            float2 v0, v1;
            v0.x = acc[mf][nf][0] + bi.x; v0.y = acc[mf][nf][1] + bi.y;
            v1.x = acc[mf][nf][2] + bi.x; v1.y = acc[mf][nf][3] + bi.y;
            *(float2*)&C[(size_t)r * ldc + cidx] = v0;
            *(float2*)&C[(size_t)(r + 8) * ldc + cidx] = v1;
        }
    }
}

// ---------------- kernel 5: batched gather-aggregate ----------------------
// 512 threads (16 warps). Two tasks per warp (half-warp each), float4/lane.
__global__ __launch_bounds__(512) void k_gather() {
    __shared__ float y_s[128 * 64];          // 32 KB
    __shared__ float wbuf[16][2][16];
    __shared__ int   nbuf[16][2][16];

    int ch = blockIdx.x, b = blockIdx.y;
    int tid = threadIdx.x;

    const float4* y4 = (const float4*)g_y;
    #pragma unroll
    for (int it = 0; it < 4; it++) {
        int idx = it * 512 + tid;
        int m = idx >> 4, c4 = idx & 15;
        ((float4*)y_s)[idx] = y4[(size_t)(b * N_SZ + m) * 128 + ch * 16 + c4];
    }
    __syncthreads();

    int wid = tid >> 5, lane = tid & 31;
    int h = lane >> 4, L = lane & 15;
    const float4* ys4 = (const float4*)y_s;

    #pragma unroll 2
    for (int it = 0; it < 12; it++) {
        int t = wid * 24 + it * 2 + h;
        int br = t >> 7, n = t & 127;
        int row = b * N_SZ + n;
        int base = (br * ROWS + row) * K_NB + L;
        wbuf[wid][h][L] = g_w[base];
        nbuf[wid][h][L] = g_ni[base] - b * N_SZ;
        __syncwarp();

        float4 acc = make_float4(0.f, 0.f, 0.f, 0.f);
        #pragma unroll
        for (int k = 0; k < 16; k++) {
            float wk = wbuf[wid][h][k];
            int   mk = nbuf[wid][h][k];
            float4 v = ys4[mk * 16 + L];
            acc.x += wk * v.x; acc.y += wk * v.y;
            acc.z += wk * v.z; acc.w += wk * v.w;
        }
        *(float4*)&g_h[(size_t)row * C_SZ + (br + 1) * D_SZ + ch * 64 + L * 4] = acc;
        __syncwarp();
    }
}

// ---------------- kernel 6: L2 norm + relu (in place) ---------------------
__global__ void k_epi() {
    int row = blockIdx.x;
    int tid = threadIdx.x;
    __shared__ float red[9];

    float4* h4 = (float4*)&g_h[(size_t)row * C_SZ];
    float4 v0 = h4[tid], v1 = h4[tid + 256];
    float ss = v0.x * v0.x + v0.y * v0.y + v0.z * v0.z + v0.w * v0.w
             + v1.x * v1.x + v1.y * v1.y + v1.z * v1.z + v1.w * v1.w;
    #pragma unroll
    for (int o = 16; o > 0; o >>= 1) ss += __shfl_down_sync(0xffffffffu, ss, o);
    if ((tid & 31) == 0) red[tid >> 5] = ss;
    __syncthreads();
    if (tid == 0) {
        float t = 0.f;
        #pragma unroll
        for (int i = 0; i < 8; i++) t += red[i];
        red[8] = 1.f / fmaxf(sqrtf(t), L2_EPS);
    }
    __syncthreads();
    float inv = red[8];

    v0.x = fmaxf(v0.x * inv, 0.f); v0.y = fmaxf(v0.y * inv, 0.f);
    v0.z = fmaxf(v0.z * inv, 0.f); v0.w = fmaxf(v0.w * inv, 0.f);
    v1.x = fmaxf(v1.x * inv, 0.f); v1.y = fmaxf(v1.y * inv, 0.f);
    v1.z = fmaxf(v1.z * inv, 0.f); v1.w = fmaxf(v1.w * inv, 0.f);
    h4[tid] = v0; h4[tid + 256] = v1;
}

// ---------------- kernel 7: channel sum / sumsq ---------------------------
__global__ void k_stats() {
    int c4 = blockIdx.x * 256 + threadIdx.x;
    int r0 = blockIdx.y * 32;
    const float4* h4 = (const float4*)g_h;
    float4 s = make_float4(0.f, 0.f, 0.f, 0.f);
    float4 q = make_float4(0.f, 0.f, 0.f, 0.f);
    #pragma unroll 4
    for (int r = r0; r < r0 + 32; r++) {
        float4 v = h4[(size_t)r * 512 + c4];
        s.x += v.x; s.y += v.y; s.z += v.z; s.w += v.w;
        q.x += v.x * v.x; q.y += v.y * v.y; q.z += v.z * v.z; q.w += v.w * v.w;
    }
    int c = c4 * 4;
    atomicAdd(&g_sum[c + 0], s.x); atomicAdd(&g_sum[c + 1], s.y);
    atomicAdd(&g_sum[c + 2], s.z); atomicAdd(&g_sum[c + 3], s.w);
    atomicAdd(&g_sumsq[c + 0], q.x); atomicAdd(&g_sumsq[c + 1], q.y);
    atomicAdd(&g_sumsq[c + 2], q.z); atomicAdd(&g_sumsq[c + 3], q.w);
}

// ---------------- kernel 8: batchnorm affine -> output --------------------
__global__ void k_final(const float* __restrict__ gamma, const float* __restrict__ beta,
                        float* __restrict__ out) {
    int gid = blockIdx.x * 256 + threadIdx.x;
    int e = gid * 4;
    int c = e & (C_SZ - 1);

    float4 h  = *(const float4*)&g_h[e];
    float4 sm = *(const float4*)&g_sum[c];
    float4 sq = *(const float4*)&g_sumsq[c];
    float4 ga = *(const float4*)&gamma[c];
    float4 be = *(const float4*)&beta[c];

    const float invn = 1.f / (float)ROWS;
    float4 o;
    { float mu = sm.x * invn; float var = sq.x * invn - mu * mu;
      o.x = (h.x - mu) * rsqrtf(var + BN_EPS) * ga.x + be.x; }
    { float mu = sm.y * invn; float var = sq.y * invn - mu * mu;
      o.y = (h.y - mu) * rsqrtf(var + BN_EPS) * ga.y + be.y; }
    { float mu = sm.z * invn; float var = sq.z * invn - mu * mu;
      o.z = (h.z - mu) * rsqrtf(var + BN_EPS) * ga.z + be.z; }
    { float mu = sm.w * invn; float var = sq.w * invn - mu * mu;
      o.w = (h.w - mu) * rsqrtf(var + BN_EPS) * ga.w + be.w; }
    *(float4*)&out[e] = o;
}

// ---------------- launch ---------------------------------------------------
extern "C" void kernel_launch(void* const* d_in, const int* in_sizes, int n_in,
                              void* d_out, int out_size) {
    const float* x     = (const float*)d_in[0];
    const int*   i1    = (const int*)  d_in[1];
    const int*   i2    = (const int*)  d_in[2];
    const int*   i3    = (const int*)  d_in[3];
    const float* Wxw   = (const float*)d_in[4];
    const float* Wxb   = (const float*)d_in[5];
    const float* Wnw   = (const float*)d_in[6];
    const float* Wnb   = (const float*)d_in[7];
    const float* Wa    = (const float*)d_in[8];
    const float* gamma = (const float*)d_in[9];
    const float* beta  = (const float*)d_in[10];
    float* out = (float*)d_out;

    k_prep<<<256, 256>>>(x, Wa);
    k_w<<<1536, 128>>>(i1, i2, i3);
    k_conv<<<1024, 256>>>(x, Wxw, Wnw);
    k_tc<<<dim3(4, 16, 2), 512>>>(Wxb, Wnb);
    k_gather<<<dim3(8, 16), 512>>>();
    k_epi<<<ROWS, 256>>>();
    k_stats<<<dim3(2, 64), 256>>>();
    k_final<<<(ROWS * C_SZ) / (256 * 4), 256>>>(gamma, beta, out);
}

// round 17
// speedup vs baseline: 1.5769x; 1.1154x over previous
#include <cuda_runtime.h>
#include <cuda_fp16.h>
#include <cstdint>

#define B_SZ   16
#define N_SZ   128
#define ROWS   2048        // B*N
#define K_NB   16
#define D_SZ   512
#define C_SZ   2048        // 4*D
#define ALPHA  0.2f
#define BN_EPS 1e-5f
#define L2_EPS 1e-12f

// ---------------- device scratch (no allocations allowed) ----------------
__device__ float g_a_self[ROWS];
__device__ float g_a_nei[ROWS];
__device__ float g_y[ROWS * D_SZ];          // x @ Wn^T + Wn_b   (4 MB)
__device__ float g_h[ROWS * C_SZ];          // concat rows       (16 MB)
__device__ float g_sum[C_SZ];
__device__ float g_sumsq[C_SZ];
__device__ float g_w[3 * ROWS * K_NB];      // softmax weights
__device__ int   g_ni[3 * ROWS * K_NB];     // neighbor row ids (global)

__device__ __half g_x16[ROWS * D_SZ];       // x (fp16)
__device__ __half g_wx16[D_SZ * D_SZ];      // Wx (fp16)
__device__ __half g_wn16[D_SZ * D_SZ];      // Wn (fp16)

// ---------------- kernel 1: attention dot products + zero stats ----------
__global__ void k_prep(const float* __restrict__ x, const float* __restrict__ Wa) {
    int tid = threadIdx.x;
    int gid = blockIdx.x * 256 + tid;
    if (gid < C_SZ) { g_sum[gid] = 0.f; g_sumsq[gid] = 0.f; }

    int wid = tid >> 5, lane = tid & 31;
    int row = blockIdx.x * 8 + wid;
    const float* xr = x + (size_t)row * D_SZ;
    float s1 = 0.f, s2 = 0.f;
    #pragma unroll 4
    for (int i = lane; i < D_SZ; i += 32) {
        float v = xr[i];
        s1 += v * Wa[i];
        s2 += v * Wa[D_SZ + i];
    }
    #pragma unroll
    for (int o = 16; o > 0; o >>= 1) {
        s1 += __shfl_down_sync(0xffffffffu, s1, o);
        s2 += __shfl_down_sync(0xffffffffu, s2, o);
    }
    if (lane == 0) { g_a_self[row] = s1; g_a_nei[row] = s2; }
}

// ---------------- kernel 2: per-(row,branch) softmax weights --------------
__global__ void k_w(const int* __restrict__ i1, const int* __restrict__ i2,
                    const int* __restrict__ i3) {
    int g = (blockIdx.x * 128 + threadIdx.x) >> 5;
    int lane = threadIdx.x & 31;
    int row = g / 3;
    int br = g - row * 3;
    int b = row >> 7, n = row & 127;
    const int* ip = (br == 0) ? i1 : (br == 1) ? i2 : i3;
    int k = lane & 15;
    int m = ip[n * K_NB + k];
    float e = g_a_self[row] + g_a_nei[b * N_SZ + m];
    e = (e > 0.f) ? e : ALPHA * e;

    float mx = e;
    #pragma unroll
    for (int o = 8; o > 0; o >>= 1) mx = fmaxf(mx, __shfl_xor_sync(0xffffffffu, mx, o, 16));
    float ev = __expf(e - mx);
    float s = ev;
    #pragma unroll
    for (int o = 8; o > 0; o >>= 1) s += __shfl_xor_sync(0xffffffffu, s, o, 16);
    float w = ev / s;

    if (lane < 16) {
        g_w[(br * ROWS + row) * K_NB + k] = w;
        g_ni[(br * ROWS + row) * K_NB + k] = b * N_SZ + m;
    }
}

// ---------------- kernel 3: fp32 -> fp16 conversion -----------------------
__global__ void k_conv(const float* __restrict__ x, const float* __restrict__ Wx,
                       const float* __restrict__ Wn) {
    int t = blockIdx.x * 256 + threadIdx.x;

    {
        float4 v = ((const float4*)x)[t];
        __half2 p0(__float2half_rn(v.x), __float2half_rn(v.y));
        __half2 p1(__float2half_rn(v.z), __float2half_rn(v.w));
        uint2 u;
        u.x = *(uint32_t*)&p0; u.y = *(uint32_t*)&p1;
        *(uint2*)&g_x16[t * 4] = u;
    }

    if (t < 131072) {
        const float* Wsrc = (t < 65536) ? Wx : Wn;
        __half* Wdst = (t < 65536) ? g_wx16 : g_wn16;
        int u = (t < 65536) ? t : t - 65536;
        float4 v = ((const float4*)Wsrc)[u];
        __half2 p0(__float2half_rn(v.x), __float2half_rn(v.y));
        __half2 p1(__float2half_rn(v.z), __float2half_rn(v.w));
        uint2 uw;
        uw.x = *(uint32_t*)&p0; uw.y = *(uint32_t*)&p1;
        *(uint2*)&Wdst[u * 4] = uw;
    }
}

// ---------------- kernel 4: tensor-core GEMMs (fp16 single pass) ----------
// Block tile 128x128, 16 warps (4m x 4n), warp tile 32x32, BK=32.
// C = x16 * W16, fp32 accumulate.
#define SSTRIDE 40

#define MMAF16(d, a, b0v, b1v) \
    asm volatile("mma.sync.aligned.m16n8k16.row.col.f32.f16.f16.f32 " \
        "{%0,%1,%2,%3}, {%4,%5,%6,%7}, {%8,%9}, {%0,%1,%2,%3};" \
        : "+f"(d[0]), "+f"(d[1]), "+f"(d[2]), "+f"(d[3]) \
        : "r"(a[0]), "r"(a[1]), "r"(a[2]), "r"(a[3]), "r"(b0v), "r"(b1v))

__device__ __forceinline__ void ldsm_x4(uint32_t* r, uint32_t a) {
    asm volatile("ldmatrix.sync.aligned.m8n8.x4.shared.b16 {%0,%1,%2,%3}, [%4];"
                 : "=r"(r[0]), "=r"(r[1]), "=r"(r[2]), "=r"(r[3]) : "r"(a));
}

__global__ __launch_bounds__(512) void k_tc(const float* __restrict__ Wxb,
                                            const float* __restrict__ Wnb) {
    __shared__ __half As[128 * SSTRIDE];
    __shared__ __half Bs[128 * SSTRIDE];

    int z = blockIdx.z;
    const __half* Wm = z ? g_wn16 : g_wx16;
    const float* bias = z ? Wnb : Wxb;
    float* C = z ? g_y : g_h;
    int ldc = z ? D_SZ : C_SZ;

    int tid = threadIdx.x;
    int lane = tid & 31;
    int wid = tid >> 5;                  // 0..15
    int wm = (wid >> 2) * 32;
    int wn = (wid & 3) * 32;
    int bm = blockIdx.y * 128;
    int bn = blockIdx.x * 128;

    int l0r = tid >> 2;                  // 0..127
    int l0c = (tid & 3) * 8;             // 0,8,16,24

    float acc[2][4][4];
    #pragma unroll
    for (int i = 0; i < 2; i++)
        #pragma unroll
        for (int j = 0; j < 4; j++)
            #pragma unroll
            for (int q = 0; q < 4; q++) acc[i][j][q] = 0.f;

    uint4 a0 = *(const uint4*)&g_x16[(size_t)(bm + l0r) * D_SZ + l0c];
    uint4 b0 = *(const uint4*)&Wm[(size_t)(bn + l0r) * D_SZ + l0c];

    int m_row = lane & 15, m_coff = (lane >> 4) * 8;

    for (int k0 = 0; k0 < D_SZ; k0 += 32) {
        __syncthreads();
        *(uint4*)&As[l0r * SSTRIDE + l0c] = a0;
        *(uint4*)&Bs[l0r * SSTRIDE + l0c] = b0;
        __syncthreads();

        if (k0 + 32 < D_SZ) {
            int kn = k0 + 32;
            a0 = *(const uint4*)&g_x16[(size_t)(bm + l0r) * D_SZ + kn + l0c];
            b0 = *(const uint4*)&Wm[(size_t)(bn + l0r) * D_SZ + kn + l0c];
        }

        #pragma unroll
        for (int ks = 0; ks < 2; ks++) {
            int kc = ks * 16;
            uint32_t af[2][4];
            #pragma unroll
            for (int mf = 0; mf < 2; mf++) {
                int off = (wm + mf * 16 + m_row) * SSTRIDE + kc + m_coff;
                ldsm_x4(af[mf], (uint32_t)__cvta_generic_to_shared(&As[off]));
            }
            uint32_t bf[4][2];
            #pragma unroll
            for (int pr = 0; pr < 2; pr++) {
                int off = (wn + pr * 16 + m_row) * SSTRIDE + kc + m_coff;
                uint32_t r[4];
                ldsm_x4(r, (uint32_t)__cvta_generic_to_shared(&Bs[off]));
                bf[pr * 2][0] = r[0]; bf[pr * 2][1] = r[2];
                bf[pr * 2 + 1][0] = r[1]; bf[pr * 2 + 1][1] = r[3];
            }
            #pragma unroll
            for (int nf = 0; nf < 4; nf++) {
                #pragma unroll
                for (int mf = 0; mf < 2; mf++) {
                    MMAF16(acc[mf][nf], af[mf], bf[nf][0], bf[nf][1]);
                }
            }
        }
    }

    #pragma unroll
    for (int nf = 0; nf < 4; nf++) {
        int cidx = bn + wn + nf * 8 + (lane & 3) * 2;
        float2 bi = *(const float2*)&bias[cidx];
        #pragma unroll
        for (int mf = 0; mf < 2; mf++) {
            int r = bm + wm + mf * 16 + (lane >> 2);
            float2 v0, v1;
            v0.x = acc[mf][nf][0] + bi.x; v0.y = acc[mf][nf][1] + bi.y;
            v1.x = acc[mf][nf][2] + bi.x; v1.y = acc[mf][nf][3] + bi.y;
            *(float2*)&C[(size_t)r * ldc + cidx] = v0;
            *(float2*)&C[(size_t)(r + 8) * ldc + cidx] = v1;
        }
    }
}

// ---------------- kernel 5: batched gather-aggregate ----------------------
// 512 threads (16 warps). Two tasks per warp (half-warp each), float4/lane.
__global__ __launch_bounds__(512) void k_gather() {
    __shared__ float y_s[128 * 64];          // 32 KB
    __shared__ float wbuf[16][2][16];
    __shared__ int   nbuf[16][2][16];

    int ch = blockIdx.x, b = blockIdx.y;
    int tid = threadIdx.x;

    const float4* y4 = (const float4*)g_y;
    #pragma unroll
    for (int it = 0; it < 4; it++) {
        int idx = it * 512 + tid;
        int m = idx >> 4, c4 = idx & 15;
        ((float4*)y_s)[idx] = y4[(size_t)(b * N_SZ + m) * 128 + ch * 16 + c4];
    }
    __syncthreads();

    int wid = tid >> 5, lane = tid & 31;
    int h = lane >> 4, L = lane & 15;
    const float4* ys4 = (const float4*)y_s;

    #pragma unroll 2
    for (int it = 0; it < 12; it++) {
        int t = wid * 24 + it * 2 + h;
        int br = t >> 7, n = t & 127;
        int row = b * N_SZ + n;
        int base = (br * ROWS + row) * K_NB + L;
        wbuf[wid][h][L] = g_w[base];
        nbuf[wid][h][L] = g_ni[base] - b * N_SZ;
        __syncwarp();

        float4 acc = make_float4(0.f, 0.f, 0.f, 0.f);
        #pragma unroll
        for (int k = 0; k < 16; k++) {
            float wk = wbuf[wid][h][k];
            int   mk = nbuf[wid][h][k];
            float4 v = ys4[mk * 16 + L];
            acc.x += wk * v.x; acc.y += wk * v.y;
            acc.z += wk * v.z; acc.w += wk * v.w;
        }
        *(float4*)&g_h[(size_t)row * C_SZ + (br + 1) * D_SZ + ch * 64 + L * 4] = acc;
        __syncwarp();
    }
}

// ---------------- kernel 6: L2 norm + relu (in place) ---------------------
__global__ void k_epi() {
    int row = blockIdx.x;
    int tid = threadIdx.x;
    __shared__ float red[9];

    float4* h4 = (float4*)&g_h[(size_t)row * C_SZ];
    float4 v0 = h4[tid], v1 = h4[tid + 256];
    float ss = v0.x * v0.x + v0.y * v0.y + v0.z * v0.z + v0.w * v0.w
             + v1.x * v1.x + v1.y * v1.y + v1.z * v1.z + v1.w * v1.w;
    #pragma unroll
    for (int o = 16; o > 0; o >>= 1) ss += __shfl_down_sync(0xffffffffu, ss, o);
    if ((tid & 31) == 0) red[tid >> 5] = ss;
    __syncthreads();
    if (tid == 0) {
        float t = 0.f;
        #pragma unroll
        for (int i = 0; i < 8; i++) t += red[i];
        red[8] = 1.f / fmaxf(sqrtf(t), L2_EPS);
    }
    __syncthreads();
    float inv = red[8];

    v0.x = fmaxf(v0.x * inv, 0.f); v0.y = fmaxf(v0.y * inv, 0.f);
    v0.z = fmaxf(v0.z * inv, 0.f); v0.w = fmaxf(v0.w * inv, 0.f);
    v1.x = fmaxf(v1.x * inv, 0.f); v1.y = fmaxf(v1.y * inv, 0.f);
    v1.z = fmaxf(v1.z * inv, 0.f); v1.w = fmaxf(v1.w * inv, 0.f);
    h4[tid] = v0; h4[tid + 256] = v1;
}

// ---------------- kernel 7: channel sum / sumsq ---------------------------
__global__ void k_stats() {
    int c4 = blockIdx.x * 256 + threadIdx.x;
    int r0 = blockIdx.y * 32;
    const float4* h4 = (const float4*)g_h;
    float4 s = make_float4(0.f, 0.f, 0.f, 0.f);
    float4 q = make_float4(0.f, 0.f, 0.f, 0.f);
    #pragma unroll 4
    for (int r = r0; r < r0 + 32; r++) {
        float4 v = h4[(size_t)r * 512 + c4];
        s.x += v.x; s.y += v.y; s.z += v.z; s.w += v.w;
        q.x += v.x * v.x; q.y += v.y * v.y; q.z += v.z * v.z; q.w += v.w * v.w;
    }
    int c = c4 * 4;
    atomicAdd(&g_sum[c + 0], s.x); atomicAdd(&g_sum[c + 1], s.y);
    atomicAdd(&g_sum[c + 2], s.z); atomicAdd(&g_sum[c + 3], s.w);
    atomicAdd(&g_sumsq[c + 0], q.x); atomicAdd(&g_sumsq[c + 1], q.y);
    atomicAdd(&g_sumsq[c + 2], q.z); atomicAdd(&g_sumsq[c + 3], q.w);
}

// ---------------- kernel 8: batchnorm affine -> output --------------------
__global__ void k_final(const float* __restrict__ gamma, const float* __restrict__ beta,
                        float* __restrict__ out) {
    int gid = blockIdx.x * 256 + threadIdx.x;
    int e = gid * 4;
    int c = e & (C_SZ - 1);

    float4 h  = *(const float4*)&g_h[e];
    float4 sm = *(const float4*)&g_sum[c];
    float4 sq = *(const float4*)&g_sumsq[c];
    float4 ga = *(const float4*)&gamma[c];
    float4 be = *(const float4*)&beta[c];

    const float invn = 1.f / (float)ROWS;
    float4 o;
    { float mu = sm.x * invn; float var = sq.x * invn - mu * mu;
      o.x = (h.x - mu) * rsqrtf(var + BN_EPS) * ga.x + be.x; }
    { float mu = sm.y * invn; float var = sq.y * invn - mu * mu;
      o.y = (h.y - mu) * rsqrtf(var + BN_EPS) * ga.y + be.y; }
    { float mu = sm.z * invn; float var = sq.z * invn - mu * mu;
      o.z = (h.z - mu) * rsqrtf(var + BN_EPS) * ga.z + be.z; }
    { float mu = sm.w * invn; float var = sq.w * invn - mu * mu;
      o.w = (h.w - mu) * rsqrtf(var + BN_EPS) * ga.w + be.w; }
    *(float4*)&out[e] = o;
}

// ---------------- launch ---------------------------------------------------
extern "C" void kernel_launch(void* const* d_in, const int* in_sizes, int n_in,
                              void* d_out, int out_size) {
    const float* x     = (const float*)d_in[0];
    const int*   i1    = (const int*)  d_in[1];
    const int*   i2    = (const int*)  d_in[2];
    const int*   i3    = (const int*)  d_in[3];
    const float* Wxw   = (const float*)d_in[4];
    const float* Wxb   = (const float*)d_in[5];
    const float* Wnw   = (const float*)d_in[6];
    const float* Wnb   = (const float*)d_in[7];
    const float* Wa    = (const float*)d_in[8];
    const float* gamma = (const float*)d_in[9];
    const float* beta  = (const float*)d_in[10];
    float* out = (float*)d_out;

    k_prep<<<256, 256>>>(x, Wa);
    k_w<<<1536, 128>>>(i1, i2, i3);
    k_conv<<<1024, 256>>>(x, Wxw, Wnw);
    k_tc<<<dim3(4, 16, 2), 512>>>(Wxb, Wnb);
    k_gather<<<dim3(8, 16), 512>>>();
    k_epi<<<ROWS, 256>>>();
    k_stats<<<dim3(2, 64), 256>>>();
    k_final<<<(ROWS * C_SZ) / (256 * 4), 256>>>(gamma, beta, out);
}